// round 7
// baseline (speedup 1.0000x reference)
#include <cuda_runtime.h>
#include <cuda_fp16.h>
#include <cstdint>

// Problem constants
#define NB      32
#define CDIM    256
#define HWN     4096
#define KCODES  1024
#define N_VEC   (NB * HWN)        // 131072
#define N_ZQ    (NB * CDIM * HWN) // 33554432

#define MARGIN  2.0e-3f           // ~7x worst-case |d_fast - d_ref| (f16 dot + fp32 bucket)

#define MT     128                // vectors per CTA
#define NSLICE 128                // codes per slice
#define NSL    (KCODES / NSLICE)  // 8 slices, all in one CTA

// ---------------- static device scratch ----------------
__device__ __half g_zh[(size_t)N_VEC * CDIM];  // f16 z, [vec][dim]
__device__ float  g_zt[(size_t)N_VEC * CDIM];  // fp32 z, [vec][dim] (exact rescore)
__device__ __half g_eh[KCODES * CDIM];         // f16 codebook [code][dim]
__device__ float  g_se[KCODES];                // ||e||^2
__device__ float  g_sz[N_VEC];                 // ||z||^2 (ref order)
__device__ int    g_idx[N_VEC];
__device__ double g_loss;

// ---------------- helpers ----------------
__device__ __forceinline__ uint32_t smem_u32(const void* p) {
    uint32_t a;
    asm("{ .reg .u64 t; cvta.to.shared.u64 t, %1; cvt.u32.u64 %0, t; }"
        : "=r"(a) : "l"(p));
    return a;
}
#define SW128(x) ((uint32_t)(x) ^ ((((uint32_t)(x)) >> 3) & 0x70u))

__device__ __forceinline__ void ldsm4(uint32_t* r, uint32_t addr) {
    asm volatile("ldmatrix.sync.aligned.m8n8.x4.shared.b16 {%0,%1,%2,%3}, [%4];"
                 : "=r"(r[0]), "=r"(r[1]), "=r"(r[2]), "=r"(r[3]) : "r"(addr));
}
__device__ __forceinline__ void mma16816(float* c, const uint32_t* a,
                                         uint32_t b0, uint32_t b1) {
    asm volatile("mma.sync.aligned.m16n8k16.row.col.f32.f16.f16.f32 "
                 "{%0,%1,%2,%3}, {%4,%5,%6,%7}, {%8,%9}, {%0,%1,%2,%3};"
                 : "+f"(c[0]), "+f"(c[1]), "+f"(c[2]), "+f"(c[3])
                 : "r"(a[0]), "r"(a[1]), "r"(a[2]), "r"(a[3]), "r"(b0), "r"(b1));
}
#define CP_ASYNC16(dst, src) \
    asm volatile("cp.async.cg.shared.global [%0], [%1], 16;" :: "r"(dst), "l"(src))
#define CP_COMMIT() asm volatile("cp.async.commit_group;" ::: "memory")
#define CP_WAIT0()  asm volatile("cp.async.wait_group 0;" ::: "memory")

// ---------------------------------------------------------------------------
// Codebook prep: f16 copy, ||e||^2, zero accumulators.
// ---------------------------------------------------------------------------
__global__ void cb_prep_kernel(const float* __restrict__ cb) {
    int n = blockIdx.x, t = threadIdx.x;
    float v = cb[n * CDIM + t];
    g_eh[n * CDIM + t] = __float2half(v);
    __shared__ float red[256];
    red[t] = __fmul_rn(v, v);
    __syncthreads();
    for (int s = 128; s > 0; s >>= 1) {
        if (t < s) red[t] = __fadd_rn(red[t], red[t + s]);
        __syncthreads();
    }
    if (t == 0) {
        g_se[n] = red[0];
        if (n == 0) g_loss = 0.0;
    }
}

// ---------------------------------------------------------------------------
// z prep: transpose [B,C,HW] -> [vec][dim]; vectorized stores.
// ---------------------------------------------------------------------------
__global__ void zprep_kernel(const float* __restrict__ z) {
    __shared__ float t[64][133];
    int tid = threadIdx.x;
    int b = blockIdx.z, c0 = blockIdx.y * 64, hw0 = blockIdx.x * 128;
    const float* src = z + ((size_t)b * CDIM + c0) * HWN + hw0;
#pragma unroll
    for (int it = 0; it < 32; it++) {
        int idx = it * 256 + tid;
        int cc = idx >> 7, h = idx & 127;
        t[cc][h] = src[(size_t)cc * HWN + h];
    }
    __syncthreads();
#pragma unroll
    for (int it = 0; it < 8; it++) {
        int idx = it * 256 + tid;
        int h = idx >> 4, cq = (idx & 15) << 2;
        float4 v = make_float4(t[cq][h], t[cq + 1][h], t[cq + 2][h], t[cq + 3][h]);
        size_t o = (size_t)(b * HWN + hw0 + h) * CDIM + c0 + cq;
        *(float4*)(g_zt + o) = v;
        __half2 p0 = __floats2half2_rn(v.x, v.y);
        __half2 p1 = __floats2half2_rn(v.z, v.w);
        uint2 u = make_uint2(*(uint32_t*)&p0, *(uint32_t*)&p1);
        *(uint2*)(g_zh + o) = u;
    }
}

// ---------------------------------------------------------------------------
// ||z||^2 in reference order (serial ascending, unfused).
// ---------------------------------------------------------------------------
__global__ void sz_kernel(const float* __restrict__ z) {
    int v  = blockIdx.x * blockDim.x + threadIdx.x;
    int b  = v >> 12, hw = v & (HWN - 1);
    const float* p = z + (size_t)b * CDIM * HWN + hw;
    float acc = 0.0f;
#pragma unroll 16
    for (int c = 0; c < CDIM; c++) {
        float x = __ldg(p + (size_t)c * HWN);
        acc = __fadd_rn(acc, __fmul_rn(x, x));
    }
    g_sz[v] = acc;
}

// ---------------------------------------------------------------------------
// Main kernel: 128 vectors x all 1024 codes per CTA, HMMA prefilter,
// 4-thread/row margin scan, in-CTA exact rescore. 512 threads.
// ---------------------------------------------------------------------------
#define SM_Z   0        // 65536
#define SM_B   65536    // 65536
#define SM_D   131072   // 68096 (128 x 133 f32)
#define SM_SE  199168   // 4096
#define SM_CD  203264   // 8192 (512 thr x 4 cand dists)
#define SM_CI  211456   // 8192
#define SM_TOT 219648
// overlays inside SM_D after the slice loop:
#define OV_MRG   (SM_D + 0)       // 512 x {runmin, cnt} = 4096
#define OV_PAIR  (SM_D + 4096)    // 2048 x u32 = 8192
#define OV_OVF   (SM_D + 12288)   // 128 x u32
#define OV_KEY   (SM_D + 12800)   // 128 x u64
#define OV_SROW  (SM_D + 13824)   // 128 x u32
#define OV_ACT   (SM_D + 14336)   // 128 x u32
#define OV_CNT   (SM_D + 14848)   // 3 ints: nslots, npairs, novf

__global__ void __launch_bounds__(512, 1)
vq_main_kernel(const float* __restrict__ cb) {
    extern __shared__ __align__(1024) char sm[];
    const uint32_t sb = smem_u32(sm);
    const int tid = threadIdx.x;
    const int wid = tid >> 5, lane = tid & 31;
    const int wm = wid >> 2, wn = wid & 3;
    const int m0 = blockIdx.x * MT;

    float* seF = (float*)(sm + SM_SE);
    float* cdF = (float*)(sm + SM_CD);
    int*   ciI = (int*)(sm + SM_CI);

    for (int i = tid; i < KCODES; i += 512) seF[i] = g_se[i];

    // z tile: 4 chunks of [128 rows x 64 dims] f16, SW128 per chunk
    for (int idx = tid; idx < 4096; idx += 512) {
        int chunk = idx >> 10, w = idx & 1023;
        int r = w >> 3, c8 = w & 7;
        uint4 v = *(const uint4*)(g_zh + (size_t)(m0 + r) * CDIM + chunk * 64 + c8 * 8);
        *(uint4*)(sm + SM_Z + chunk * 16384 + SW128(r * 128 + c8 * 16)) = v;
    }
    // B slice 0
    for (int idx = tid; idx < 4096; idx += 512) {
        int chunk = idx >> 10, w = idx & 1023;
        int r = w >> 3, c8 = w & 7;
        uint4 v = *(const uint4*)(g_eh + (size_t)r * CDIM + chunk * 64 + c8 * 8);
        *(uint4*)(sm + SM_B + chunk * 16384 + SW128(r * 128 + c8 * 16)) = v;
    }

    // per-thread persistent scan state: quarter q of row r
    const int srow = tid & 127, sq = tid >> 7;
    float szr = g_sz[m0 + srow];
    float runmin = 3.4e38f;
    int cnt = 0;
    float* cd = cdF + tid * 4;
    int*   ci = ciI + tid * 4;

    const int q = lane >> 3, lr = lane & 7;
    const int arow = wm * 32 + ((q & 1) << 3) + lr;
    const int acol = (q >> 1) << 4;
    const int brow = wn * 32 + ((q >> 1) << 3) + lr;
    const int bcol = (q & 1) << 4;

    __syncthreads();

    for (int ns = 0; ns < NSL; ns++) {
        float acc[2][4][4];
#pragma unroll
        for (int a = 0; a < 2; a++)
#pragma unroll
            for (int b = 0; b < 4; b++)
#pragma unroll
                for (int c = 0; c < 4; c++) acc[a][b][c] = 0.0f;

#pragma unroll
        for (int k16 = 0; k16 < 16; k16++) {
            const uint32_t abase = sb + SM_Z + (k16 >> 2) * 16384;
            const uint32_t bbase = sb + SM_B + (k16 >> 2) * 16384;
            const int kb = (k16 & 3) * 32;
            uint32_t afr[2][4], bfr[2][4];
            ldsm4(afr[0], abase + SW128(arow * 128 + kb + acol));
            ldsm4(afr[1], abase + SW128((arow + 16) * 128 + kb + acol));
            ldsm4(bfr[0], bbase + SW128(brow * 128 + kb + bcol));
            ldsm4(bfr[1], bbase + SW128((brow + 16) * 128 + kb + bcol));
#pragma unroll
            for (int mt = 0; mt < 2; mt++)
#pragma unroll
                for (int ni = 0; ni < 4; ni++)
                    mma16816(acc[mt][ni], afr[mt],
                             bfr[ni >> 1][(ni & 1) * 2], bfr[ni >> 1][(ni & 1) * 2 + 1]);
        }
        __syncthreads();  // all B reads done; D free (prev scan synced)

        // dump dists + prefetch next B slice via cp.async
        float* D = (float*)(sm + SM_D);
        {
            const int g = lane >> 2, tg = lane & 3;
#pragma unroll
            for (int mt = 0; mt < 2; mt++) {
                int r0 = wm * 32 + mt * 16 + g;
#pragma unroll
                for (int ni = 0; ni < 4; ni++) {
                    int c = wn * 32 + ni * 8 + tg * 2;
                    D[r0 * 133 + c]           = acc[mt][ni][0];
                    D[r0 * 133 + c + 1]       = acc[mt][ni][1];
                    D[(r0 + 8) * 133 + c]     = acc[mt][ni][2];
                    D[(r0 + 8) * 133 + c + 1] = acc[mt][ni][3];
                }
            }
        }
        if (ns + 1 < NSL) {
#pragma unroll
            for (int it = 0; it < 8; it++) {
                int idx = tid + it * 512;
                int chunk = idx >> 10, w = idx & 1023;
                int r = w >> 3, c8 = w & 7;
                CP_ASYNC16(sb + SM_B + chunk * 16384 + SW128(r * 128 + c8 * 16),
                           g_eh + (size_t)((ns + 1) * NSLICE + r) * CDIM + chunk * 64 + c8 * 8);
            }
            CP_COMMIT();
        }
        __syncthreads();  // D visible to scanners

        // scan: 4 threads per row, 32 codes each; state persists across slices
        {
            const int n0 = ns * NSLICE + sq * 32;
            const float* dr = D + srow * 133 + sq * 32;
            const float* ses = seF + n0;
            for (int j = 0; j < 32; j++) {
                float d = fmaf(-2.0f, dr[j], szr + ses[j]);
                if (d < runmin + MARGIN) {
                    runmin = fminf(runmin, d);
                    if (cnt < 4) { cd[cnt] = d; ci[cnt] = n0 + j; cnt++; }
                    else if (cnt == 4) {
                        int w = 0;
#pragma unroll
                        for (int t = 0; t < 4; t++)
                            if (cd[t] < runmin + MARGIN) { cd[w] = cd[t]; ci[w] = ci[t]; w++; }
                        cnt = w;
                        if (cnt < 4) { cd[cnt] = d; ci[cnt] = n0 + j; cnt++; }
                        else cnt = 5;  // overflow sentinel
                    }
                }
            }
        }
        if (ns + 1 < NSL) CP_WAIT0();
        __syncthreads();  // scan done (D reusable), next B ready
    }

    // ---- in-CTA resolution ----
    float* MRGf   = (float*)(sm + OV_MRG);
    uint32_t* pairs = (uint32_t*)(sm + OV_PAIR);
    uint32_t* ovfl  = (uint32_t*)(sm + OV_OVF);
    unsigned long long* keys = (unsigned long long*)(sm + OV_KEY);
    int* slotrow = (int*)(sm + OV_SROW);
    int* actA    = (int*)(sm + OV_ACT);
    int* cnt3    = (int*)(sm + OV_CNT);   // [0]=nslots [1]=npairs [2]=novf

    MRGf[tid * 2]     = runmin;
    MRGf[tid * 2 + 1] = __int_as_float(cnt);
    if (tid == 0) { cnt3[0] = 0; cnt3[1] = 0; cnt3[2] = 0; }
    __syncthreads();

    if (tid < MT) {
        const int r = tid;
        float gmin = 3.4e38f;
        bool ovf = false;
#pragma unroll
        for (int qq = 0; qq < 4; qq++) {
            int t2 = qq * 128 + r;
            gmin = fminf(gmin, MRGf[t2 * 2]);
            if (__float_as_int(MRGf[t2 * 2 + 1]) > 4) ovf = true;
        }
        if (ovf) {
            int slot = atomicAdd(&cnt3[0], 1);
            slotrow[slot] = r;
            int o = atomicAdd(&cnt3[2], 1);
            ovfl[o] = (uint32_t)((slot << 7) | r);
            actA[r] = 2;
        } else {
            int u = 0, uidx = 0;
#pragma unroll
            for (int qq = 0; qq < 4; qq++) {
                int t2 = qq * 128 + r;
                int c = __float_as_int(MRGf[t2 * 2 + 1]);
                for (int s = 0; s < c; s++)
                    if (cdF[t2 * 4 + s] < gmin + MARGIN) { u++; uidx = ciI[t2 * 4 + s]; }
            }
            if (u == 1) {
                g_idx[m0 + r] = uidx;
                actA[r] = 0;
            } else {
                actA[r] = 1;
                keys[r] = ~0ull;
                int slot = atomicAdd(&cnt3[0], 1);
                slotrow[slot] = r;
#pragma unroll
                for (int qq = 0; qq < 4; qq++) {
                    int t2 = qq * 128 + r;
                    int c = __float_as_int(MRGf[t2 * 2 + 1]);
                    for (int s = 0; s < c; s++)
                        if (cdF[t2 * 4 + s] < gmin + MARGIN) {
                            int p = atomicAdd(&cnt3[1], 1);
                            pairs[p] = (uint32_t)((slot << 17) | (r << 10) | ciI[t2 * 4 + s]);
                        }
                }
            }
        }
    }
    __syncthreads();

    const int nslots = cnt3[0], npairs = cnt3[1], novf = cnt3[2];
    float* stage = (float*)sm;  // overlays Z+B: 128 rows x 256 f32 = 128KB

    // stage fp32 z rows for ambiguous rows
    for (int i = tid; i < nslots * CDIM; i += 512) {
        int slot = i >> 8, k = i & 255;
        stage[slot * CDIM + k] = g_zt[(size_t)(m0 + slotrow[slot]) * CDIM + k];
    }
    __syncthreads();

    // exact pair rescore (bitwise reference recipe), thread per pair
    for (int p = tid; p < npairs; p += 512) {
        uint32_t e = pairs[p];
        int slot = (e >> 17) & 127, row = (e >> 10) & 127, code = e & 1023;
        const float* zs = stage + slot * CDIM;
        const float* er = cb + (size_t)code * CDIM;
        float acc = 0.0f;
#pragma unroll 16
        for (int k = 0; k < CDIM; k++) acc = __fmaf_rn(zs[k], __ldg(er + k), acc);
        float d = __fsub_rn(__fadd_rn(g_sz[m0 + row], seF[code]), __fmul_rn(2.0f, acc));
        unsigned long long kk = ((unsigned long long)__float_as_uint(d) << 32) | (unsigned)code;
        atomicMin(&keys[row], kk);
    }

    // exact full rescan for overflow rows, warp per row
    for (int o = wid; o < novf; o += 16) {
        uint32_t e = ovfl[o];
        int slot = e >> 7, row = e & 127;
        const float* zs = stage + slot * CDIM;
        float sz = g_sz[m0 + row];
        float bd = __int_as_float(0x7f800000);
        int bi = 0x7fffffff;
        for (int c = lane; c < KCODES; c += 32) {
            const float* er = cb + (size_t)c * CDIM;
            float acc = 0.0f;
#pragma unroll 16
            for (int k = 0; k < CDIM; k++) acc = __fmaf_rn(zs[k], __ldg(er + k), acc);
            float d = __fsub_rn(__fadd_rn(sz, seF[c]), __fmul_rn(2.0f, acc));
            if (d < bd) { bd = d; bi = c; }  // ascending c: strict < keeps lowest
        }
#pragma unroll
        for (int off = 16; off > 0; off >>= 1) {
            float od = __shfl_xor_sync(0xffffffffu, bd, off);
            int   oi = __shfl_xor_sync(0xffffffffu, bi, off);
            if (od < bd || (od == bd && oi < bi)) { bd = od; bi = oi; }
        }
        if (lane == 0) g_idx[m0 + row] = bi;
    }
    __syncthreads();

    if (tid < MT && actA[tid] == 1)
        g_idx[m0 + tid] = (int)(keys[tid] & 0xffffffffu);
}

// ---------------------------------------------------------------------------
// Gather + straight-through + loss (+ indices).
// ---------------------------------------------------------------------------
__global__ void gather_kernel(const float* __restrict__ z,
                              const float* __restrict__ cb,
                              float* __restrict__ out, int mode) {
    int v  = blockIdx.x * blockDim.x + threadIdx.x;
    int b  = v >> 12, hw = v & (HWN - 1);
    int idx = g_idx[v];
    const float4* crow = (const float4*)(cb + idx * CDIM);
    float lsum = 0.0f;
    for (int cc = 0; cc < CDIM / 8; cc++) {
        float4 e0 = crow[cc * 2];
        float4 e1 = crow[cc * 2 + 1];
        float er[8] = {e0.x, e0.y, e0.z, e0.w, e1.x, e1.y, e1.z, e1.w};
#pragma unroll
        for (int j = 0; j < 8; j++) {
            int c = cc * 8 + j;
            size_t zi = (((size_t)b * CDIM + c) << 12) + hw;
            float zv = z[zi];
            float t  = __fsub_rn(er[j], zv);
            out[zi]  = __fadd_rn(zv, t);
            lsum = __fmaf_rn(t, t, lsum);
        }
    }
    for (int o = 16; o > 0; o >>= 1)
        lsum += __shfl_down_sync(0xffffffffu, lsum, o);
    if ((threadIdx.x & 31) == 0) atomicAdd(&g_loss, (double)lsum);
    if (mode >= 2) out[N_ZQ + 2 + v] = (float)idx;
}

__global__ void finalize_kernel(float* __restrict__ out, int mode) {
    if (mode >= 1) {
        float mean = (float)(g_loss / (double)N_ZQ);
        out[N_ZQ]     = mean;
        out[N_ZQ + 1] = 0.25f * mean;
    }
}

// ---------------------------------------------------------------------------
extern "C" void kernel_launch(void* const* d_in, const int* in_sizes, int n_in,
                              void* d_out, int out_size) {
    const float* z  = (const float*)d_in[0];
    const float* cb = (const float*)d_in[1];
    float* out = (float*)d_out;

    int mode = 0;
    if (out_size >= N_ZQ + 2) mode = 1;
    if (out_size >= N_ZQ + 2 + N_VEC) mode = 2;

    cudaFuncSetAttribute(vq_main_kernel,
                         cudaFuncAttributeMaxDynamicSharedMemorySize, SM_TOT);

    cb_prep_kernel<<<KCODES, 256>>>(cb);
    zprep_kernel<<<dim3(HWN / 128, CDIM / 64, NB), 256>>>(z);
    sz_kernel<<<N_VEC / 256, 256>>>(z);
    vq_main_kernel<<<N_VEC / MT, 512, SM_TOT>>>(cb);
    gather_kernel<<<N_VEC / 256, 256>>>(z, cb, out, mode);
    finalize_kernel<<<1, 1>>>(out, mode);
}